// round 11
// baseline (speedup 1.0000x reference)
#include <cuda_runtime.h>
#include <cuda_bf16.h>
#include <cstdint>

// ---------------- problem constants ----------------
#define D_IN    4096
#define D_OUT   64
#define N_B     32
#define N_S     2048
#define N_LORA  16

#define TILE_M    256
#define NTHREADS  256
#define N_PAIR    (D_IN / 32)        // 128 k32 slots (2 x k16 chunks each)

// ---- smem pipeline: 2 slots, one k32 chunk-pair per slot ----
#define A_ROW_B   144                 // 32 floats + 4 pad floats (16B-aligned rows)
#define A_BYTES   (TILE_M * A_ROW_B)  // 36864
#define B_OFF     A_BYTES
#define B_BYTES   8192                // 2 chunks * 256 lanes * uint4
#define SLOT_BYTES (A_BYTES + B_BYTES)      // 45056
#define SMEM_TOTAL (2 * SLOT_BYTES)         // 90112 (88 KB) -> 2 CTAs/SM

// ---------------- weight scratch: fragment-layout tf32 ----------------
// [lora][kchunk(256)][ntile(8)*32 + lane] -> uint4 {b_k(g), b_k(g+4), b_k(g+8), b_k(g+12)}
__device__ __align__(16) uint4 g_wfrag[(size_t)N_LORA * 256 * 256];

// ---------------- helpers ----------------
__device__ __forceinline__ uint32_t smem_u32(const void* p) {
    uint32_t a;
    asm("{ .reg .u64 t; cvta.to.shared.u64 t, %1; cvt.u32.u64 %0, t; }" : "=r"(a) : "l"(p));
    return a;
}

__device__ __forceinline__ uint32_t tf32_rna(float v) {
    uint32_t r;
    asm("cvt.rna.tf32.f32 %0, %1;" : "=r"(r) : "f"(v));
    return r;
}

// m16n8k8 tf32 MMA, fp32 accumulate
__device__ __forceinline__ void mma1688(float* c, const uint32_t* a, uint32_t b0, uint32_t b1) {
    asm volatile(
        "mma.sync.aligned.m16n8k8.row.col.f32.tf32.tf32.f32 "
        "{%0,%1,%2,%3}, {%4,%5,%6,%7}, {%8,%9}, {%0,%1,%2,%3};"
        : "+f"(c[0]), "+f"(c[1]), "+f"(c[2]), "+f"(c[3])
        : "r"(a[0]), "r"(a[1]), "r"(a[2]), "r"(a[3]), "r"(b0), "r"(b1));
}

__device__ __forceinline__ void cp_async16(uint32_t dst, const void* src) {
    asm volatile("cp.async.cg.shared.global [%0], [%1], 16;" :: "r"(dst), "l"(src) : "memory");
}

__device__ __forceinline__ float lds_f32(uint32_t a) {
    float v;
    asm volatile("ld.shared.f32 %0, [%1];" : "=f"(v) : "r"(a));
    return v;
}

// ---------------- prep: weight[lora][k][n] fp32 -> tf32 fragment scratch ----------------
__global__ void __launch_bounds__(256)
lora_prep_kernel(const float* __restrict__ w) {
    __shared__ float sw[16][68];   // [k_local][n], padded
    const int t = threadIdx.x;
    const float* src = w + (size_t)blockIdx.x * 1024;   // 16 k-rows x 64 n
    float4 v = *(const float4*)(src + t * 4);
    const int kr = t >> 4, nc = (t & 15) * 4;
    sw[kr][nc + 0] = v.x; sw[kr][nc + 1] = v.y;
    sw[kr][nc + 2] = v.z; sw[kr][nc + 3] = v.w;
    __syncthreads();

    const int nt = t >> 5, l = t & 31;
    const int g = l & 3, nl = l >> 2;
    const int n = nt * 8 + nl;
    g_wfrag[(size_t)blockIdx.x * 256 + t] = make_uint4(
        tf32_rna(sw[g + 0][n]),  tf32_rna(sw[g + 4][n]),
        tf32_rna(sw[g + 8][n]),  tf32_rna(sw[g + 12][n]));
}

// ---------------- main kernel ----------------
// issue one k32 slot: A tile (256 rows x 32 fp32) + B frags (2 x 256 uint4) via cp.async
// per warp-instruction: 4 rows x 8 segs = 4 full 128B lines, fully coalesced
__device__ __forceinline__ void issue_slot(uint32_t sbase, const float* xcta,
                                           const uint4* wsrc, int p, int t) {
    const uint32_t slot = sbase + (uint32_t)(p & 1) * SLOT_BYTES;
    const int r0 = t >> 3, seg = t & 7;
    const float* asrc = xcta + (size_t)r0 * D_IN + p * 32 + seg * 4;
    const uint32_t adst = slot + (uint32_t)(r0 * A_ROW_B + seg * 16);
    #pragma unroll
    for (int q = 0; q < 8; ++q)
        cp_async16(adst + q * 32 * A_ROW_B, asrc + (size_t)q * 32 * D_IN);
    cp_async16(slot + B_OFF + (uint32_t)t * 16,        wsrc + (size_t)(2 * p) * 256 + t);
    cp_async16(slot + B_OFF + 4096 + (uint32_t)t * 16, wsrc + (size_t)(2 * p + 1) * 256 + t);
    asm volatile("cp.async.commit_group;" ::: "memory");
}

__global__ void __launch_bounds__(NTHREADS, 2)
lora_main_kernel(const float* __restrict__ x, const int* __restrict__ ids,
                 float* __restrict__ out) {
    extern __shared__ uint4 smem_buf[];
    const uint32_t sbase = smem_u32(smem_buf);
    const int t = threadIdx.x, wid = t >> 5, l = t & 31;
    const int g = l & 3, nl = l >> 2;

    const int b = blockIdx.x >> 3;
    const int mbase = (blockIdx.x & 7) * TILE_M;
    const int aid = __ldg(ids + b);
    const uint4* wsrc = g_wfrag + (size_t)aid * 256 * 256;
    const float* xcta = x + ((size_t)b * N_S + mbase) * D_IN;

    float acc[2][8][4];
    #pragma unroll
    for (int mt = 0; mt < 2; ++mt)
        #pragma unroll
        for (int nt = 0; nt < 8; ++nt)
            #pragma unroll
            for (int i = 0; i < 4; ++i)
                acc[mt][nt][i] = 0.0f;

    // prologue: fill slot 0
    issue_slot(sbase, xcta, wsrc, 0, t);

    // per-thread A smem base: row = wid*32 + nl, col = g floats
    const uint32_t abase = sbase + (uint32_t)((wid * 32 + nl) * A_ROW_B + g * 4);

    for (int p = 0; p < N_PAIR; ++p) {
        asm volatile("cp.async.wait_group 0;" ::: "memory");
        __syncthreads();   // slot p visible; all warps done reading slot p-1's buffer
        if (p + 1 < N_PAIR)
            issue_slot(sbase, xcta, wsrc, p + 1, t);

        const uint32_t slot = (uint32_t)(p & 1) * SLOT_BYTES;

        // two k16 chunks per slot, no barrier between them
        #pragma unroll
        for (int ci = 0; ci < 2; ++ci) {
            // ---- A fragments: fp32 -> tf32 (rna). step0 = +0/+16, step1 = +32/+48 ----
            uint32_t a0[2][4], a1[2][4];
            #pragma unroll
            for (int mt = 0; mt < 2; ++mt) {
                const uint32_t ab = abase + slot + (uint32_t)(mt * 16 * A_ROW_B + ci * 64);
                a0[mt][0] = tf32_rna(lds_f32(ab));                        // (row,   g)
                a0[mt][1] = tf32_rna(lds_f32(ab + 8 * A_ROW_B));          // (row+8, g)
                a0[mt][2] = tf32_rna(lds_f32(ab + 16));                   // (row,   g+4)
                a0[mt][3] = tf32_rna(lds_f32(ab + 8 * A_ROW_B + 16));     // (row+8, g+4)
                a1[mt][0] = tf32_rna(lds_f32(ab + 32));                   // (row,   g+8)
                a1[mt][1] = tf32_rna(lds_f32(ab + 8 * A_ROW_B + 32));     // (row+8, g+8)
                a1[mt][2] = tf32_rna(lds_f32(ab + 48));                   // (row,   g+12)
                a1[mt][3] = tf32_rna(lds_f32(ab + 8 * A_ROW_B + 48));     // (row+8, g+12)
            }

            // ---- B from smem, 2 k8-step mma per (mt, nt) ----
            const uint32_t bb = sbase + slot + B_OFF + (uint32_t)(ci * 4096 + l * 16);
            #pragma unroll
            for (int nt = 0; nt < 8; ++nt) {
                uint32_t b00, b01, b10, b11;
                asm volatile("ld.shared.v4.b32 {%0,%1,%2,%3}, [%4];"
                             : "=r"(b00), "=r"(b01), "=r"(b10), "=r"(b11)
                             : "r"(bb + (uint32_t)(nt * 512)));
                #pragma unroll
                for (int mt = 0; mt < 2; ++mt) {
                    mma1688(acc[mt][nt], a0[mt], b00, b01);  // k0..k0+7
                    mma1688(acc[mt][nt], a1[mt], b10, b11);  // k0+8..k0+15
                }
            }
        }
    }

    // ---- epilogue ----
    #pragma unroll
    for (int mt = 0; mt < 2; ++mt) {
        const int row = mbase + wid * 32 + mt * 16 + nl;
        float* o = out + ((size_t)b * N_S + row) * D_OUT + 2 * g;
        #pragma unroll
        for (int nt = 0; nt < 8; ++nt) {
            *(float2*)(o + nt * 8)             = make_float2(acc[mt][nt][0], acc[mt][nt][1]);
            *(float2*)(o + nt * 8 + 8 * D_OUT) = make_float2(acc[mt][nt][2], acc[mt][nt][3]);
        }
    }
}

// ---------------- launch ----------------
extern "C" void kernel_launch(void* const* d_in, const int* in_sizes, int n_in,
                              void* d_out, int out_size) {
    const float* x  = (const float*)d_in[0];
    const int* ids  = (const int*)d_in[1];
    const float* w  = (const float*)d_in[2];
    float* out      = (float*)d_out;

    cudaFuncSetAttribute(lora_main_kernel,
                         cudaFuncAttributeMaxDynamicSharedMemorySize, SMEM_TOTAL);

    lora_prep_kernel<<<N_LORA * 256, 256>>>(w);
    lora_main_kernel<<<N_B * (N_S / TILE_M), NTHREADS, SMEM_TOTAL>>>(x, ids, out);
}

// round 12
// speedup vs baseline: 1.6885x; 1.6885x over previous
#include <cuda_runtime.h>
#include <cuda_fp16.h>
#include <cstdint>

// ---------------- problem constants ----------------
#define D_IN    4096
#define D_OUT   64
#define N_B     32
#define N_S     2048
#define N_LORA  16

#define TILE_M    256
#define NTHREADS  256
#define N_KCHUNK  (D_IN / 16)        // 256 k16 chunks

// ---- smem pipeline: 4 stages, one k16 chunk per stage (R9 structure) ----
#define N_STAGES  4
#define A_ROW_B   80                  // 16 floats + 4 pad floats (16B-aligned rows)
#define A_BYTES   (TILE_M * A_ROW_B)  // 20480
#define B_OFF     A_BYTES
#define B_BYTES   2048                // 128 uint4 (4 ntile-pairs x 32 lanes)
#define STAGE_BYTES (A_BYTES + B_BYTES)       // 22528
#define SMEM_TOTAL  (N_STAGES * STAGE_BYTES)  // 90112 (88 KB) -> 2 CTAs/SM

// ---------------- weight scratch: fragment-layout fp16 ----------------
// [lora][kchunk(256)][j(4)*32 + lane] -> uint4:
//   x = b0(nt=2j), y = b1(nt=2j), z = b0(nt=2j+1), w = b1(nt=2j+1)
// m16n8k16 B frag (lane: g=l&3, nl=l>>2, col n = nt*8+nl):
//   b0 = fp16x2 {B[2g][n], B[2g+1][n]},  b1 = fp16x2 {B[2g+8][n], B[2g+9][n]}
__device__ __align__(16) uint4 g_wfrag[(size_t)N_LORA * 256 * 128];

// ---------------- helpers ----------------
__device__ __forceinline__ uint32_t smem_u32(const void* p) {
    uint32_t a;
    asm("{ .reg .u64 t; cvta.to.shared.u64 t, %1; cvt.u32.u64 %0, t; }" : "=r"(a) : "l"(p));
    return a;
}

// pack two fp32 -> fp16x2, v0 in low 16 bits
__device__ __forceinline__ uint32_t f16x2_pack(float v0, float v1) {
    uint32_t r;
    asm("cvt.rn.f16x2.f32 %0, %1, %2;" : "=r"(r) : "f"(v1), "f"(v0));
    return r;
}

// m16n8k16 fp16 MMA, fp32 accumulate
__device__ __forceinline__ void mma16816(float* c, const uint32_t* a, uint32_t b0, uint32_t b1) {
    asm volatile(
        "mma.sync.aligned.m16n8k16.row.col.f32.f16.f16.f32 "
        "{%0,%1,%2,%3}, {%4,%5,%6,%7}, {%8,%9}, {%0,%1,%2,%3};"
        : "+f"(c[0]), "+f"(c[1]), "+f"(c[2]), "+f"(c[3])
        : "r"(a[0]), "r"(a[1]), "r"(a[2]), "r"(a[3]), "r"(b0), "r"(b1));
}

__device__ __forceinline__ void cp_async16(uint32_t dst, const void* src) {
    asm volatile("cp.async.cg.shared.global [%0], [%1], 16;" :: "r"(dst), "l"(src) : "memory");
}

__device__ __forceinline__ void lds_f2(float2& v, uint32_t a) {
    asm volatile("ld.shared.v2.f32 {%0,%1}, [%2];" : "=f"(v.x), "=f"(v.y) : "r"(a));
}

// ---------------- prep: weight[lora][k][n] fp32 -> fp16 fragment scratch ----------------
__global__ void __launch_bounds__(256)
lora_prep_kernel(const float* __restrict__ w) {
    __shared__ float sw[16][68];   // [k_local][n], padded
    const int t = threadIdx.x;
    const float* src = w + (size_t)blockIdx.x * 1024;   // 16 k-rows x 64 n
    float4 v = *(const float4*)(src + t * 4);
    const int kr = t >> 4, nc = (t & 15) * 4;
    sw[kr][nc + 0] = v.x; sw[kr][nc + 1] = v.y;
    sw[kr][nc + 2] = v.z; sw[kr][nc + 3] = v.w;
    __syncthreads();

    if (t < 128) {
        const int j = t >> 5, l = t & 31;
        const int g = l & 3, nl = l >> 2;
        const int n0 = (2 * j) * 8 + nl;
        const int n1 = n0 + 8;
        g_wfrag[(size_t)blockIdx.x * 128 + t] = make_uint4(
            f16x2_pack(sw[2 * g][n0],     sw[2 * g + 1][n0]),
            f16x2_pack(sw[2 * g + 8][n0], sw[2 * g + 9][n0]),
            f16x2_pack(sw[2 * g][n1],     sw[2 * g + 1][n1]),
            f16x2_pack(sw[2 * g + 8][n1], sw[2 * g + 9][n1]));
    }
}

// ---------------- main kernel ----------------
// issue one stage: A tile (256 rows x 16 fp32) + B frags (128 uint4) via cp.async
__device__ __forceinline__ void issue_stage(uint32_t sbase, const float* xcta,
                                            const uint4* wsrc, int s, int t) {
    const uint32_t stg = sbase + (uint32_t)(s & (N_STAGES - 1)) * STAGE_BYTES;
    const int r0 = t >> 2, seg = t & 3;
    const float* asrc = xcta + (size_t)r0 * D_IN + s * 16 + seg * 4;
    uint32_t adst = stg + (uint32_t)(r0 * A_ROW_B + seg * 16);
    #pragma unroll
    for (int q = 0; q < 4; ++q)
        cp_async16(adst + q * 64 * A_ROW_B, asrc + (size_t)q * 64 * D_IN);
    if (t < 128)
        cp_async16(stg + B_OFF + (uint32_t)t * 16, wsrc + (size_t)s * 128 + t);
    asm volatile("cp.async.commit_group;" ::: "memory");
}

__global__ void __launch_bounds__(NTHREADS, 2)
lora_main_kernel(const float* __restrict__ x, const int* __restrict__ ids,
                 float* __restrict__ out) {
    extern __shared__ uint4 smem_buf[];
    const uint32_t sbase = smem_u32(smem_buf);
    const int t = threadIdx.x, wid = t >> 5, l = t & 31;
    const int g = l & 3, nl = l >> 2;

    const int b = blockIdx.x >> 3;
    const int mbase = (blockIdx.x & 7) * TILE_M;
    const int aid = __ldg(ids + b);
    const uint4* wsrc = g_wfrag + (size_t)aid * 256 * 128;
    const float* xcta = x + ((size_t)b * N_S + mbase) * D_IN;

    float acc[2][8][4];
    #pragma unroll
    for (int mt = 0; mt < 2; ++mt)
        #pragma unroll
        for (int nt = 0; nt < 8; ++nt)
            #pragma unroll
            for (int i = 0; i < 4; ++i)
                acc[mt][nt][i] = 0.0f;

    // prologue: fill N_STAGES-1 stages
    #pragma unroll
    for (int s = 0; s < N_STAGES - 1; ++s)
        issue_stage(sbase, xcta, wsrc, s, t);

    // per-thread A smem base: row = wid*32 + nl, fp32 col pair at 2g -> byte g*8
    const uint32_t abase = sbase + (uint32_t)((wid * 32 + nl) * A_ROW_B + g * 8);

    for (int s = 0; s < N_KCHUNK; ++s) {
        asm volatile("cp.async.wait_group %0;" :: "n"(N_STAGES - 2) : "memory");
        __syncthreads();   // stage s visible; all warps done reading stage s-1's buffer
        if (s + N_STAGES - 1 < N_KCHUNK)
            issue_stage(sbase, xcta, wsrc, s + N_STAGES - 1, t);

        const uint32_t stg = (uint32_t)(s & (N_STAGES - 1)) * STAGE_BYTES;

        // ---- A fragments from smem: fp32 -> fp16x2 ----
        // a0 = (row, k2g..2g+1), a1 = (row+8, same), a2 = (row, k2g+8..), a3 = (row+8, ..)
        uint32_t a[2][4];
        #pragma unroll
        for (int mt = 0; mt < 2; ++mt) {
            const uint32_t ab = abase + stg + (uint32_t)(mt * 16 * A_ROW_B);
            float2 f0, f1, f2, f3;
            lds_f2(f0, ab);                         // (row,   2g)
            lds_f2(f2, ab + 8 * A_ROW_B);           // (row+8, 2g)
            lds_f2(f1, ab + 32);                    // (row,   2g+8)
            lds_f2(f3, ab + 8 * A_ROW_B + 32);      // (row+8, 2g+8)
            a[mt][0] = f16x2_pack(f0.x, f0.y);
            a[mt][1] = f16x2_pack(f2.x, f2.y);
            a[mt][2] = f16x2_pack(f1.x, f1.y);
            a[mt][3] = f16x2_pack(f3.x, f3.y);
        }

        // ---- B from smem: one LDS.128 per ntile-pair, 1 fp16 k16 mma per (mt, nt) ----
        const uint32_t bb = sbase + stg + B_OFF + (uint32_t)(l * 16);
        #pragma unroll
        for (int j = 0; j < 4; ++j) {
            uint32_t b00, b01, b10, b11;
            asm volatile("ld.shared.v4.b32 {%0,%1,%2,%3}, [%4];"
                         : "=r"(b00), "=r"(b01), "=r"(b10), "=r"(b11)
                         : "r"(bb + (uint32_t)(j * 512)));
            #pragma unroll
            for (int mt = 0; mt < 2; ++mt) {
                mma16816(acc[mt][2 * j],     a[mt], b00, b01);
                mma16816(acc[mt][2 * j + 1], a[mt], b10, b11);
            }
        }
    }

    // ---- epilogue ----
    #pragma unroll
    for (int mt = 0; mt < 2; ++mt) {
        const int row = mbase + wid * 32 + mt * 16 + nl;
        float* o = out + ((size_t)b * N_S + row) * D_OUT + 2 * g;
        #pragma unroll
        for (int nt = 0; nt < 8; ++nt) {
            *(float2*)(o + nt * 8)             = make_float2(acc[mt][nt][0], acc[mt][nt][1]);
            *(float2*)(o + nt * 8 + 8 * D_OUT) = make_float2(acc[mt][nt][2], acc[mt][nt][3]);
        }
    }
}

// ---------------- launch ----------------
extern "C" void kernel_launch(void* const* d_in, const int* in_sizes, int n_in,
                              void* d_out, int out_size) {
    const float* x  = (const float*)d_in[0];
    const int* ids  = (const int*)d_in[1];
    const float* w  = (const float*)d_in[2];
    float* out      = (float*)d_out;

    cudaFuncSetAttribute(lora_main_kernel,
                         cudaFuncAttributeMaxDynamicSharedMemorySize, SMEM_TOTAL);

    lora_prep_kernel<<<N_LORA * 256, 256>>>(w);
    lora_main_kernel<<<N_B * (N_S / TILE_M), NTHREADS, SMEM_TOTAL>>>(x, ids, out);
}

// round 14
// speedup vs baseline: 1.7983x; 1.0651x over previous
#include <cuda_runtime.h>
#include <cuda_fp16.h>
#include <cstdint>

// ---------------- problem constants ----------------
#define D_IN    4096
#define D_OUT   64
#define N_B     32
#define N_S     2048
#define N_LORA  16

#define TILE_M    256
#define NTHREADS  256
#define N_KCHUNK  (D_IN / 16)        // 256 k16 chunks

// ---- smem: A-only 4-stage ring, warp-private rows, NO CTA barriers in mainloop ----
#define N_STAGES  4
#define A_ROW_B   80                  // 16 floats + 4 pad floats (16B-aligned rows)
#define A_BYTES   (TILE_M * A_ROW_B)  // 20480 per stage
#define SMEM_TOTAL  (N_STAGES * A_BYTES)   // 81920 (80 KB) -> 2 CTAs/SM

// ---------------- weight scratch: fragment-layout fp16 (read via LDG from L2) ----------------
// [lora][kchunk(256)][j(4)*32 + lane] -> uint4:
//   x = b0(nt=2j), y = b1(nt=2j), z = b0(nt=2j+1), w = b1(nt=2j+1)
__device__ __align__(16) uint4 g_wfrag[(size_t)N_LORA * 256 * 128];

// ---------------- helpers ----------------
__device__ __forceinline__ uint32_t smem_u32(const void* p) {
    uint32_t a;
    asm("{ .reg .u64 t; cvta.to.shared.u64 t, %1; cvt.u32.u64 %0, t; }" : "=r"(a) : "l"(p));
    return a;
}

// pack two fp32 -> fp16x2, v0 in low 16 bits
__device__ __forceinline__ uint32_t f16x2_pack(float v0, float v1) {
    uint32_t r;
    asm("cvt.rn.f16x2.f32 %0, %1, %2;" : "=r"(r) : "f"(v1), "f"(v0));
    return r;
}

// m16n8k16 fp16 MMA, fp32 accumulate
__device__ __forceinline__ void mma16816(float* c, const uint32_t* a, uint32_t b0, uint32_t b1) {
    asm volatile(
        "mma.sync.aligned.m16n8k16.row.col.f32.f16.f16.f32 "
        "{%0,%1,%2,%3}, {%4,%5,%6,%7}, {%8,%9}, {%0,%1,%2,%3};"
        : "+f"(c[0]), "+f"(c[1]), "+f"(c[2]), "+f"(c[3])
        : "r"(a[0]), "r"(a[1]), "r"(a[2]), "r"(a[3]), "r"(b0), "r"(b1));
}

__device__ __forceinline__ void cp_async16(uint32_t dst, const void* src) {
    asm volatile("cp.async.cg.shared.global [%0], [%1], 16;" :: "r"(dst), "l"(src) : "memory");
}

__device__ __forceinline__ void lds_f2(float2& v, uint32_t a) {
    asm volatile("ld.shared.v2.f32 {%0,%1}, [%2];" : "=f"(v.x), "=f"(v.y) : "r"(a));
}

__device__ __forceinline__ uint4 ldg_nc_v4(const uint4* p) {
    uint4 v;
    asm volatile("ld.global.nc.v4.b32 {%0,%1,%2,%3}, [%4];"
                 : "=r"(v.x), "=r"(v.y), "=r"(v.z), "=r"(v.w) : "l"(p));
    return v;
}

// ---------------- prep: weight[lora][k][n] fp32 -> fp16 fragment scratch ----------------
__global__ void __launch_bounds__(256)
lora_prep_kernel(const float* __restrict__ w) {
    __shared__ float sw[16][68];   // [k_local][n], padded
    const int t = threadIdx.x;
    const float* src = w + (size_t)blockIdx.x * 1024;   // 16 k-rows x 64 n
    float4 v = *(const float4*)(src + t * 4);
    const int kr = t >> 4, nc = (t & 15) * 4;
    sw[kr][nc + 0] = v.x; sw[kr][nc + 1] = v.y;
    sw[kr][nc + 2] = v.z; sw[kr][nc + 3] = v.w;
    __syncthreads();

    if (t < 128) {
        const int j = t >> 5, l = t & 31;
        const int g = l & 3, nl = l >> 2;
        const int n0 = (2 * j) * 8 + nl;
        const int n1 = n0 + 8;
        g_wfrag[(size_t)blockIdx.x * 128 + t] = make_uint4(
            f16x2_pack(sw[2 * g][n0],     sw[2 * g + 1][n0]),
            f16x2_pack(sw[2 * g + 8][n0], sw[2 * g + 9][n0]),
            f16x2_pack(sw[2 * g][n1],     sw[2 * g + 1][n1]),
            f16x2_pack(sw[2 * g + 8][n1], sw[2 * g + 9][n1]));
    }
}

// ---------------- main kernel ----------------
// per-WARP stage issue: warp w copies only its own 32 A rows (2 KB) for chunk s.
// lane l: row offset r = l>>2 (+8q), seg = l&3 -> 4 cp.async.16 per lane.
__device__ __forceinline__ void issue_stage_warp(uint32_t sbase, const float* xcta,
                                                 int s, int wid, int l) {
    const uint32_t stg = sbase + (uint32_t)(s & (N_STAGES - 1)) * A_BYTES;
    const int r = (l >> 2), seg = l & 3;
    const int row0 = wid * 32 + r;
    const float* asrc = xcta + (size_t)row0 * D_IN + s * 16 + seg * 4;
    const uint32_t adst = stg + (uint32_t)(row0 * A_ROW_B + seg * 16);
    #pragma unroll
    for (int q = 0; q < 4; ++q)
        cp_async16(adst + q * 8 * A_ROW_B, asrc + (size_t)q * 8 * D_IN);
    asm volatile("cp.async.commit_group;" ::: "memory");
}

__global__ void __launch_bounds__(NTHREADS, 2)
lora_main_kernel(const float* __restrict__ x, const int* __restrict__ ids,
                 float* __restrict__ out) {
    extern __shared__ uint4 smem_buf[];
    const uint32_t sbase = smem_u32(smem_buf);
    const int t = threadIdx.x, wid = t >> 5, l = t & 31;
    const int g = l & 3, nl = l >> 2;

    const int b = blockIdx.x >> 3;
    const int mbase = (blockIdx.x & 7) * TILE_M;
    const int aid = __ldg(ids + b);
    const uint4* wsrc = g_wfrag + (size_t)aid * 256 * 128 + l;
    const float* xcta = x + ((size_t)b * N_S + mbase) * D_IN;

    float acc[2][8][4];
    #pragma unroll
    for (int mt = 0; mt < 2; ++mt)
        #pragma unroll
        for (int nt = 0; nt < 8; ++nt)
            #pragma unroll
            for (int i = 0; i < 4; ++i)
                acc[mt][nt][i] = 0.0f;

    // prologue: each warp fills its rows of stages 0..2 (3 per-thread commit groups)
    #pragma unroll
    for (int s = 0; s < N_STAGES - 1; ++s)
        issue_stage_warp(sbase, xcta, s, wid, l);

    // per-thread A smem base: row = wid*32 + nl, fp32 col pair at 2g -> byte g*8
    const uint32_t abase = sbase + (uint32_t)((wid * 32 + nl) * A_ROW_B + g * 8);

    for (int s = 0; s < N_KCHUNK; ++s) {
        // warp-private pacing: oldest group (chunk s) complete; 2 stay in flight
        asm volatile("cp.async.wait_group %0;" :: "n"(N_STAGES - 2) : "memory");
        __syncwarp();   // cross-lane visibility of this warp's A rows
        if (s + N_STAGES - 1 < N_KCHUNK)
            issue_stage_warp(sbase, xcta, s + N_STAGES - 1, wid, l);

        // ---- B straight from L2 (no smem): 4x LDG.128, land under A phase ----
        const uint4* bp = wsrc + (size_t)s * 128;
        uint4 bv0 = ldg_nc_v4(bp);
        uint4 bv1 = ldg_nc_v4(bp + 32);
        uint4 bv2 = ldg_nc_v4(bp + 64);
        uint4 bv3 = ldg_nc_v4(bp + 96);

        const uint32_t stg = (uint32_t)(s & (N_STAGES - 1)) * A_BYTES;

        // ---- A fragments from smem: fp32 -> fp16x2 ----
        uint32_t a[2][4];
        #pragma unroll
        for (int mt = 0; mt < 2; ++mt) {
            const uint32_t ab = abase + stg + (uint32_t)(mt * 16 * A_ROW_B);
            float2 f0, f1, f2, f3;
            lds_f2(f0, ab);                         // (row,   2g)
            lds_f2(f2, ab + 8 * A_ROW_B);           // (row+8, 2g)
            lds_f2(f1, ab + 32);                    // (row,   2g+8)
            lds_f2(f3, ab + 8 * A_ROW_B + 32);      // (row+8, 2g+8)
            a[mt][0] = f16x2_pack(f0.x, f0.y);
            a[mt][1] = f16x2_pack(f2.x, f2.y);
            a[mt][2] = f16x2_pack(f1.x, f1.y);
            a[mt][3] = f16x2_pack(f3.x, f3.y);
        }

        // ---- 16 MMAs per warp ----
        #pragma unroll
        for (int mt = 0; mt < 2; ++mt) {
            mma16816(acc[mt][0], a[mt], bv0.x, bv0.y);
            mma16816(acc[mt][1], a[mt], bv0.z, bv0.w);
            mma16816(acc[mt][2], a[mt], bv1.x, bv1.y);
            mma16816(acc[mt][3], a[mt], bv1.z, bv1.w);
            mma16816(acc[mt][4], a[mt], bv2.x, bv2.y);
            mma16816(acc[mt][5], a[mt], bv2.z, bv2.w);
            mma16816(acc[mt][6], a[mt], bv3.x, bv3.y);
            mma16816(acc[mt][7], a[mt], bv3.z, bv3.w);
        }
    }

    // ---- epilogue ----
    #pragma unroll
    for (int mt = 0; mt < 2; ++mt) {
        const int row = mbase + wid * 32 + mt * 16 + nl;
        float* o = out + ((size_t)b * N_S + row) * D_OUT + 2 * g;
        #pragma unroll
        for (int nt = 0; nt < 8; ++nt) {
            *(float2*)(o + nt * 8)             = make_float2(acc[mt][nt][0], acc[mt][nt][1]);
            *(float2*)(o + nt * 8 + 8 * D_OUT) = make_float2(acc[mt][nt][2], acc[mt][nt][3]);
        }
    }
}

// ---------------- launch ----------------
extern "C" void kernel_launch(void* const* d_in, const int* in_sizes, int n_in,
                              void* d_out, int out_size) {
    const float* x  = (const float*)d_in[0];
    const int* ids  = (const int*)d_in[1];
    const float* w  = (const float*)d_in[2];
    float* out      = (float*)d_out;

    cudaFuncSetAttribute(lora_main_kernel,
                         cudaFuncAttributeMaxDynamicSharedMemorySize, SMEM_TOTAL);

    lora_prep_kernel<<<N_LORA * 256, 256>>>(w);
    lora_main_kernel<<<N_B * (N_S / TILE_M), NTHREADS, SMEM_TOTAL>>>(x, ids, out);
}

// round 16
// speedup vs baseline: 2.0815x; 1.1574x over previous
#include <cuda_runtime.h>
#include <cuda_fp16.h>
#include <cstdint>

// ---------------- problem constants ----------------
#define D_IN    4096
#define D_OUT   64
#define N_B     32
#define N_S     2048
#define N_LORA  16

#define TILE_M    256
#define NTHREADS  256
#define N_SLOT    (D_IN / 32)        // 128 k32 slots (2 x k16 sub-chunks each)

// ---- smem: A-only 3-slot ring of k32 tiles, warp-private rows, no CTA barriers ----
#define N_STAGES  3
#define A_ROW_B   144                 // 32 floats + 4 pad floats (16B-aligned rows)
#define A_BYTES   (TILE_M * A_ROW_B)  // 36864 per slot
#define SMEM_TOTAL  (N_STAGES * A_BYTES)   // 110592 (108 KB) -> 2 CTAs/SM

// ---------------- weight scratch: fragment-layout fp16 (read via LDG from L2) ----------------
// [lora][kchunk16(256)][j(4)*32 + lane] -> uint4:
//   x = b0(nt=2j), y = b1(nt=2j), z = b0(nt=2j+1), w = b1(nt=2j+1)
__device__ __align__(16) uint4 g_wfrag[(size_t)N_LORA * 256 * 128];

// ---------------- helpers ----------------
__device__ __forceinline__ uint32_t smem_u32(const void* p) {
    uint32_t a;
    asm("{ .reg .u64 t; cvta.to.shared.u64 t, %1; cvt.u32.u64 %0, t; }" : "=r"(a) : "l"(p));
    return a;
}

// pack two fp32 -> fp16x2, v0 in low 16 bits
__device__ __forceinline__ uint32_t f16x2_pack(float v0, float v1) {
    uint32_t r;
    asm("cvt.rn.f16x2.f32 %0, %1, %2;" : "=r"(r) : "f"(v1), "f"(v0));
    return r;
}

// m16n8k16 fp16 MMA, fp32 accumulate
__device__ __forceinline__ void mma16816(float* c, const uint32_t* a, uint32_t b0, uint32_t b1) {
    asm volatile(
        "mma.sync.aligned.m16n8k16.row.col.f32.f16.f16.f32 "
        "{%0,%1,%2,%3}, {%4,%5,%6,%7}, {%8,%9}, {%0,%1,%2,%3};"
        : "+f"(c[0]), "+f"(c[1]), "+f"(c[2]), "+f"(c[3])
        : "r"(a[0]), "r"(a[1]), "r"(a[2]), "r"(a[3]), "r"(b0), "r"(b1));
}

__device__ __forceinline__ void cp_async16(uint32_t dst, const void* src) {
    asm volatile("cp.async.cg.shared.global [%0], [%1], 16;" :: "r"(dst), "l"(src) : "memory");
}

__device__ __forceinline__ void lds_f2(float2& v, uint32_t a) {
    asm volatile("ld.shared.v2.f32 {%0,%1}, [%2];" : "=f"(v.x), "=f"(v.y) : "r"(a));
}

__device__ __forceinline__ uint4 ldg_nc_v4(const uint4* p) {
    uint4 v;
    asm volatile("ld.global.nc.v4.b32 {%0,%1,%2,%3}, [%4];"
                 : "=r"(v.x), "=r"(v.y), "=r"(v.z), "=r"(v.w) : "l"(p));
    return v;
}

// ---------------- prep: weight[lora][k][n] fp32 -> fp16 fragment scratch ----------------
__global__ void __launch_bounds__(256)
lora_prep_kernel(const float* __restrict__ w) {
    __shared__ float sw[16][68];   // [k_local][n], padded
    const int t = threadIdx.x;
    const float* src = w + (size_t)blockIdx.x * 1024;   // 16 k-rows x 64 n
    float4 v = *(const float4*)(src + t * 4);
    const int kr = t >> 4, nc = (t & 15) * 4;
    sw[kr][nc + 0] = v.x; sw[kr][nc + 1] = v.y;
    sw[kr][nc + 2] = v.z; sw[kr][nc + 3] = v.w;
    __syncthreads();

    if (t < 128) {
        const int j = t >> 5, l = t & 31;
        const int g = l & 3, nl = l >> 2;
        const int n0 = (2 * j) * 8 + nl;
        const int n1 = n0 + 8;
        g_wfrag[(size_t)blockIdx.x * 128 + t] = make_uint4(
            f16x2_pack(sw[2 * g][n0],     sw[2 * g + 1][n0]),
            f16x2_pack(sw[2 * g + 8][n0], sw[2 * g + 9][n0]),
            f16x2_pack(sw[2 * g][n1],     sw[2 * g + 1][n1]),
            f16x2_pack(sw[2 * g + 8][n1], sw[2 * g + 9][n1]));
    }
}

// ---------------- main kernel ----------------
// per-WARP k32 slot issue: warp w copies its 32 A rows as FULL 128B lines.
// lane l: r0 = l>>3 (rows r0+4q), seg = l&7 -> lanes 0-7 cover one row, coalesced.
__device__ __forceinline__ void issue_slot_warp(uint32_t sbase, const float* xcta,
                                                int s, int st, int wid, int l) {
    const uint32_t stg = sbase + (uint32_t)st * A_BYTES;
    const int r0 = l >> 3, seg = l & 7;
    const int row0 = wid * 32 + r0;
    const float* asrc = xcta + (size_t)row0 * D_IN + s * 32 + seg * 4;
    const uint32_t adst = stg + (uint32_t)(row0 * A_ROW_B + seg * 16);
    #pragma unroll
    for (int q = 0; q < 8; ++q)
        cp_async16(adst + q * 4 * A_ROW_B, asrc + (size_t)q * 4 * D_IN);
    asm volatile("cp.async.commit_group;" ::: "memory");
}

// one k16 sub-chunk body (identical structure to R14's proven body)
__device__ __forceinline__ void sub_body(const uint4* bp, uint32_t ab_base, int ci,
                                         float acc[2][8][4]) {
    // ---- B straight from L2: 4x LDG.128 ----
    uint4 bv0 = ldg_nc_v4(bp);
    uint4 bv1 = ldg_nc_v4(bp + 32);
    uint4 bv2 = ldg_nc_v4(bp + 64);
    uint4 bv3 = ldg_nc_v4(bp + 96);

    // ---- A fragments from smem: fp32 -> fp16x2 ----
    uint32_t a[2][4];
    #pragma unroll
    for (int mt = 0; mt < 2; ++mt) {
        const uint32_t ab = ab_base + (uint32_t)(mt * 16 * A_ROW_B + ci * 64);
        float2 f0, f1, f2, f3;
        lds_f2(f0, ab);                         // (row,   2g)
        lds_f2(f2, ab + 8 * A_ROW_B);           // (row+8, 2g)
        lds_f2(f1, ab + 32);                    // (row,   2g+8)
        lds_f2(f3, ab + 8 * A_ROW_B + 32);      // (row+8, 2g+8)
        a[mt][0] = f16x2_pack(f0.x, f0.y);
        a[mt][1] = f16x2_pack(f2.x, f2.y);
        a[mt][2] = f16x2_pack(f1.x, f1.y);
        a[mt][3] = f16x2_pack(f3.x, f3.y);
    }

    // ---- 16 MMAs per warp ----
    #pragma unroll
    for (int mt = 0; mt < 2; ++mt) {
        mma16816(acc[mt][0], a[mt], bv0.x, bv0.y);
        mma16816(acc[mt][1], a[mt], bv0.z, bv0.w);
        mma16816(acc[mt][2], a[mt], bv1.x, bv1.y);
        mma16816(acc[mt][3], a[mt], bv1.z, bv1.w);
        mma16816(acc[mt][4], a[mt], bv2.x, bv2.y);
        mma16816(acc[mt][5], a[mt], bv2.z, bv2.w);
        mma16816(acc[mt][6], a[mt], bv3.x, bv3.y);
        mma16816(acc[mt][7], a[mt], bv3.z, bv3.w);
    }
}

__global__ void __launch_bounds__(NTHREADS, 2)
lora_main_kernel(const float* __restrict__ x, const int* __restrict__ ids,
                 float* __restrict__ out) {
    extern __shared__ uint4 smem_buf[];
    const uint32_t sbase = smem_u32(smem_buf);
    const int t = threadIdx.x, wid = t >> 5, l = t & 31;
    const int g = l & 3, nl = l >> 2;

    const int b = blockIdx.x >> 3;
    const int mbase = (blockIdx.x & 7) * TILE_M;
    const int aid = __ldg(ids + b);
    const uint4* wsrc = g_wfrag + (size_t)aid * 256 * 128 + l;
    const float* xcta = x + ((size_t)b * N_S + mbase) * D_IN;

    float acc[2][8][4];
    #pragma unroll
    for (int mt = 0; mt < 2; ++mt)
        #pragma unroll
        for (int nt = 0; nt < 8; ++nt)
            #pragma unroll
            for (int i = 0; i < 4; ++i)
                acc[mt][nt][i] = 0.0f;

    // prologue: each warp fills its rows of slots 0,1 (2 per-thread commit groups)
    issue_slot_warp(sbase, xcta, 0, 0, wid, l);
    issue_slot_warp(sbase, xcta, 1, 1, wid, l);

    // per-thread A smem base: row = wid*32 + nl, fp32 col pair at 2g -> byte g*8
    const uint32_t abase = sbase + (uint32_t)((wid * 32 + nl) * A_ROW_B + g * 8);

    // Wait-count invariant: reading chunk s requires allowed_pending =
    // committed - (s+1). committed = min(s+2, N_SLOT)  =>  1 for all
    // s <= N_SLOT-2, but 0 for the FINAL iteration (the R15 race). Peel it.
    int st = 0;            // ring slot of chunk s
    int st_w = 2;          // ring slot for the slot being issued (s+2)
    for (int s = 0; s < N_SLOT - 1; ++s) {
        // warp-private pacing: slot s complete; slot s+1 may remain in flight
        asm volatile("cp.async.wait_group 1;" ::: "memory");
        __syncwarp();   // cross-lane visibility of this warp's A rows
        if (s + 2 < N_SLOT)
            issue_slot_warp(sbase, xcta, s + 2, st_w, wid, l);

        const uint32_t ab_base = abase + (uint32_t)st * A_BYTES;
        const uint4* bp = wsrc + (size_t)(2 * s) * 128;
        sub_body(bp,       ab_base, 0, acc);   // k16 sub-chunk 0
        sub_body(bp + 128, ab_base, 1, acc);   // k16 sub-chunk 1

        st   = (st   == 2) ? 0 : st + 1;
        st_w = (st_w == 2) ? 0 : st_w + 1;
    }

    // final slot: ALL copies must be complete before reading (wait_group 0)
    {
        asm volatile("cp.async.wait_group 0;" ::: "memory");
        __syncwarp();
        const uint32_t ab_base = abase + (uint32_t)st * A_BYTES;
        const uint4* bp = wsrc + (size_t)(2 * (N_SLOT - 1)) * 128;
        sub_body(bp,       ab_base, 0, acc);
        sub_body(bp + 128, ab_base, 1, acc);
    }

    // ---- epilogue ----
    #pragma unroll
    for (int mt = 0; mt < 2; ++mt) {
        const int row = mbase + wid * 32 + mt * 16 + nl;
        float* o = out + ((size_t)b * N_S + row) * D_OUT + 2 * g;
        #pragma unroll
        for (int nt = 0; nt < 8; ++nt) {
            *(float2*)(o + nt * 8)             = make_float2(acc[mt][nt][0], acc[mt][nt][1]);
            *(float2*)(o + nt * 8 + 8 * D_OUT) = make_float2(acc[mt][nt][2], acc[mt][nt][3]);
        }
    }
}

// ---------------- launch ----------------
extern "C" void kernel_launch(void* const* d_in, const int* in_sizes, int n_in,
                              void* d_out, int out_size) {
    const float* x  = (const float*)d_in[0];
    const int* ids  = (const int*)d_in[1];
    const float* w  = (const float*)d_in[2];
    float* out      = (float*)d_out;

    cudaFuncSetAttribute(lora_main_kernel,
                         cudaFuncAttributeMaxDynamicSharedMemorySize, SMEM_TOTAL);

    lora_prep_kernel<<<N_LORA * 256, 256>>>(w);
    lora_main_kernel<<<N_B * (N_S / TILE_M), NTHREADS, SMEM_TOTAL>>>(x, ids, out);
}